// round 7
// baseline (speedup 1.0000x reference)
#include <cuda_runtime.h>
#include <math.h>

// ---------------------------------------------------------------------------
// Problem constants
// ---------------------------------------------------------------------------
#define C_EMBD 1024
#define T_SEQ  2048
#define NBATCH 8
#define BT     (NBATCH * T_SEQ)          // 16384 rows total

// ---------------------------------------------------------------------------
// Scratch (device globals: the sanctioned no-alloc workaround)
// ---------------------------------------------------------------------------
__device__ float g_h[(size_t)BT * C_EMBD];                 // hidden / attn-out (64 MB)
__device__ float g_q[(size_t)BT * C_EMBD];                 // 64 MB
__device__ float g_k[(size_t)BT * C_EMBD];                 // 64 MB
__device__ float g_v[(size_t)BT * C_EMBD];                 // 64 MB
__device__ float g_p[(size_t)NBATCH * T_SEQ * T_SEQ];      // masked scores (128 MB)

// ---------------------------------------------------------------------------
// Packed f32x2 helpers (Blackwell FFMA2 — PTX-only path, 2x fp32 FMA rate)
// ---------------------------------------------------------------------------
__device__ __forceinline__ unsigned long long pk2(float lo, float hi) {
    unsigned long long r;
    asm("mov.b64 %0, {%1, %2};" : "=l"(r) : "f"(lo), "f"(hi));
    return r;
}
__device__ __forceinline__ void ffma2(unsigned long long& d,
                                      unsigned long long a, unsigned long long b) {
    asm("fma.rn.f32x2 %0, %1, %2, %0;" : "+l"(d) : "l"(a), "l"(b));
}
__device__ __forceinline__ float2 upk2(unsigned long long v) {
    float2 f;
    asm("mov.b64 {%0, %1}, %2;" : "=f"(f.x), "=f"(f.y) : "l"(v));
    return f;
}

// ---------------------------------------------------------------------------
// GEMM: C[M,N] = A[M,K] @ (B or B^T)[K,N]  (+ epilogue)
//   BM=BN=128, BK=16, 256 threads, 8x8 per thread (packed as 8x4 f32x2).
//   Epilogues: 0=none, 1=+bias, 2=+bias then exact GELU, 3=causal mask*scale
//   CAUSAL_K: limit K-loop to (by+1)*BM (PV consumes only valid P columns).
// ---------------------------------------------------------------------------
#define BM 128
#define BN 128
#define BK 16

__device__ __forceinline__ void st_tile_tr(float (&S)[BK][BM], int ar, int ac,
                                           float4 a0, float4 a1) {
    S[ac + 0][ar] = a0.x; S[ac + 1][ar] = a0.y;
    S[ac + 2][ar] = a0.z; S[ac + 3][ar] = a0.w;
    S[ac + 0][ar + 64] = a1.x; S[ac + 1][ar + 64] = a1.y;
    S[ac + 2][ar + 64] = a1.z; S[ac + 3][ar + 64] = a1.w;
}

__device__ __forceinline__ void mm_tile(const float (&As)[BK][BM],
                                        const float (&Bs)[BK][BN],
                                        int ty, int tx,
                                        unsigned long long (&acc)[8][4]) {
#pragma unroll
    for (int kk = 0; kk < BK; ++kk) {
        float4 av0 = *(const float4*)&As[kk][ty * 8];
        float4 av1 = *(const float4*)&As[kk][ty * 8 + 4];
        ulonglong2 bA = *(const ulonglong2*)&Bs[kk][tx * 8];
        ulonglong2 bB = *(const ulonglong2*)&Bs[kk][tx * 8 + 4];
        float a8[8] = {av0.x, av0.y, av0.z, av0.w, av1.x, av1.y, av1.z, av1.w};
        unsigned long long bq[4] = {bA.x, bA.y, bB.x, bB.y};
#pragma unroll
        for (int i = 0; i < 8; ++i) {
            unsigned long long ai = pk2(a8[i], a8[i]);
#pragma unroll
            for (int jp = 0; jp < 4; ++jp) ffma2(acc[i][jp], ai, bq[jp]);
        }
    }
}

template <bool TRANS_B, int EPI, bool CAUSAL_K>
__global__ void gemm_kernel(const float* __restrict__ Ag,
                            const float* __restrict__ Bg,
                            const float* __restrict__ bias,
                            float* __restrict__ Cg,
                            int N, int K,
                            long long sA, long long sB, long long sC,
                            float oscale) {
    const int bx = blockIdx.x, by = blockIdx.y, bz = blockIdx.z;
    if (EPI == 3 && bx > by) return;   // causal skip: tiles fully above diagonal

    const float* A = Ag + (long long)bz * sA + (long long)by * BM * K;
    const float* B;
    if (TRANS_B) B = Bg + (long long)bz * sB + (long long)bx * BN * K;
    else         B = Bg + (long long)bz * sB + bx * BN;
    float* Cc = Cg + (long long)bz * sC;

    int Keff = K;
    if (CAUSAL_K) { int lim = (by + 1) * BM; Keff = lim < K ? lim : K; }
    const int nt = Keff / BK;

    __shared__ float As[2][BK][BM];
    __shared__ float Bs[2][BK][BN];

    const int tid = threadIdx.x;
    const int ar = tid >> 2;            // 0..63
    const int ac = (tid & 3) << 2;      // 0,4,8,12
    const int br = tid >> 5;            // 0..7
    const int bc = (tid & 31) << 2;     // 0..124
    const int tx = tid & 15;
    const int ty = tid >> 4;

    unsigned long long acc[8][4];
#pragma unroll
    for (int i = 0; i < 8; ++i)
#pragma unroll
        for (int j = 0; j < 4; ++j) acc[i][j] = 0ULL;

    // ---- load tile 0 ----
    {
        float4 a0 = *(const float4*)(A + (long long)ar * K + ac);
        float4 a1 = *(const float4*)(A + (long long)(ar + 64) * K + ac);
        st_tile_tr(As[0], ar, ac, a0, a1);
        if (TRANS_B) {
            float4 b0 = *(const float4*)(B + (long long)ar * K + ac);
            float4 b1 = *(const float4*)(B + (long long)(ar + 64) * K + ac);
            st_tile_tr(Bs[0], ar, ac, b0, b1);
        } else {
            float4 b0 = *(const float4*)(B + (long long)br * N + bc);
            float4 b1 = *(const float4*)(B + (long long)(br + 8) * N + bc);
            *(float4*)&Bs[0][br][bc]     = b0;
            *(float4*)&Bs[0][br + 8][bc] = b1;
        }
    }
    __syncthreads();

    int cur = 0;
    for (int kt = 1; kt < nt; ++kt) {
        // prefetch tile kt into registers
        const float* Ak = A + kt * BK;
        float4 pa0 = *(const float4*)(Ak + (long long)ar * K + ac);
        float4 pa1 = *(const float4*)(Ak + (long long)(ar + 64) * K + ac);
        float4 pb0, pb1;
        if (TRANS_B) {
            const float* Bk = B + kt * BK;
            pb0 = *(const float4*)(Bk + (long long)ar * K + ac);
            pb1 = *(const float4*)(Bk + (long long)(ar + 64) * K + ac);
        } else {
            const float* Bk = B + (long long)(kt * BK) * N;
            pb0 = *(const float4*)(Bk + (long long)br * N + bc);
            pb1 = *(const float4*)(Bk + (long long)(br + 8) * N + bc);
        }

        mm_tile(As[cur], Bs[cur], ty, tx, acc);

        const int nxt = cur ^ 1;
        st_tile_tr(As[nxt], ar, ac, pa0, pa1);
        if (TRANS_B) {
            st_tile_tr(Bs[nxt], ar, ac, pb0, pb1);
        } else {
            *(float4*)&Bs[nxt][br][bc]     = pb0;
            *(float4*)&Bs[nxt][br + 8][bc] = pb1;
        }
        __syncthreads();
        cur = nxt;
    }
    mm_tile(As[cur], Bs[cur], ty, tx, acc);

    // ---- epilogue ----
    const int crow = by * BM + ty * 8;
    const int ccol = bx * BN + tx * 8;
    float bv[8];
    if (EPI == 1 || EPI == 2) {
#pragma unroll
        for (int j = 0; j < 8; ++j) bv[j] = bias[ccol + j];
    }
#pragma unroll
    for (int i = 0; i < 8; ++i) {
        float c[8];
#pragma unroll
        for (int jp = 0; jp < 4; ++jp) {
            float2 f = upk2(acc[i][jp]);
            c[2 * jp] = f.x; c[2 * jp + 1] = f.y;
        }
#pragma unroll
        for (int j = 0; j < 8; ++j) {
            float vv = c[j];
            if (EPI == 1) {
                vv += bv[j];
            } else if (EPI == 2) {
                vv += bv[j];
                vv = 0.5f * vv * (1.0f + erff(vv * 0.7071067811865476f));  // exact GELU
            } else if (EPI == 3) {
                vv = (crow + i >= ccol + j) ? vv * oscale : 0.0f;          // tril * 1/scale
            }
            c[j] = vv;
        }
        float* cp = Cc + (long long)(crow + i) * N + ccol;
        *(float4*)cp       = make_float4(c[0], c[1], c[2], c[3]);
        *(float4*)(cp + 4) = make_float4(c[4], c[5], c[6], c[7]);
    }
}

// ---------------------------------------------------------------------------
// LayerNorm over last dim (C=1024): one block (256 thr) per row, two-pass.
// ---------------------------------------------------------------------------
__global__ void ln_kernel(const float* __restrict__ in,
                          const float* __restrict__ w,
                          const float* __restrict__ bb,
                          float* __restrict__ out) {
    const long long row = blockIdx.x;
    const int tid = threadIdx.x;
    const float4* ip = (const float4*)(in + row * C_EMBD);
    float4 v = ip[tid];

    __shared__ float red[8];
    __shared__ float sval;

    float s = v.x + v.y + v.z + v.w;
#pragma unroll
    for (int o = 16; o > 0; o >>= 1) s += __shfl_xor_sync(0xffffffffu, s, o);
    if ((tid & 31) == 0) red[tid >> 5] = s;
    __syncthreads();
    if (tid == 0) {
        float t = red[0] + red[1] + red[2] + red[3] + red[4] + red[5] + red[6] + red[7];
        sval = t * (1.0f / (float)C_EMBD);
    }
    __syncthreads();
    const float mu = sval;

    const float dx = v.x - mu, dy = v.y - mu, dz = v.z - mu, dw = v.w - mu;
    float ss = dx * dx + dy * dy + dz * dz + dw * dw;
#pragma unroll
    for (int o = 16; o > 0; o >>= 1) ss += __shfl_xor_sync(0xffffffffu, ss, o);
    __syncthreads();
    if ((tid & 31) == 0) red[tid >> 5] = ss;
    __syncthreads();
    if (tid == 0) {
        float t = red[0] + red[1] + red[2] + red[3] + red[4] + red[5] + red[6] + red[7];
        sval = rsqrtf(t * (1.0f / (float)C_EMBD) + 1e-5f);
    }
    __syncthreads();
    const float rstd = sval;

    float4 wv = ((const float4*)w)[tid];
    float4 bv = ((const float4*)bb)[tid];
    float4 o;
    o.x = dx * rstd * wv.x + bv.x;
    o.y = dy * rstd * wv.y + bv.y;
    o.z = dz * rstd * wv.z + bv.z;
    o.w = dw * rstd * wv.w + bv.w;
    ((float4*)(out + row * C_EMBD))[tid] = o;
}

// ---------------------------------------------------------------------------
// Launch
// ---------------------------------------------------------------------------
extern "C" void kernel_launch(void* const* d_in, const int* in_sizes, int n_in,
                              void* d_out, int out_size) {
    (void)in_sizes; (void)n_in; (void)out_size;

    const float* x   = (const float*)d_in[0];
    const float* W1q = (const float*)d_in[1];
    const float* b1q = (const float*)d_in[2];
    const float* W2q = (const float*)d_in[3];
    const float* b2q = (const float*)d_in[4];
    const float* W1k = (const float*)d_in[5];
    const float* b1k = (const float*)d_in[6];
    const float* W2k = (const float*)d_in[7];
    const float* b2k = (const float*)d_in[8];
    const float* W1v = (const float*)d_in[9];
    const float* b1v = (const float*)d_in[10];
    const float* W2v = (const float*)d_in[11];
    const float* b2v = (const float*)d_in[12];
    const float* lnw = (const float*)d_in[13];
    const float* lnb = (const float*)d_in[14];
    float* out = (float*)d_out;

    float *h, *q, *k, *v, *p;
    cudaGetSymbolAddress((void**)&h, g_h);
    cudaGetSymbolAddress((void**)&q, g_q);
    cudaGetSymbolAddress((void**)&k, g_k);
    cudaGetSymbolAddress((void**)&v, g_v);
    cudaGetSymbolAddress((void**)&p, g_p);

    const dim3 blk(256);
    const dim3 gM(C_EMBD / BN, BT / BM);          // (8, 128) — MLP GEMMs
    const dim3 gQK(T_SEQ / BN, T_SEQ / BM, NBATCH);  // (16, 16, 8)
    const dim3 gPV(C_EMBD / BN, T_SEQ / BM, NBATCH); // (8, 16, 8)

    const long long sTC = (long long)T_SEQ * C_EMBD;
    const long long sTT = (long long)T_SEQ * T_SEQ;
    const float inv_scale = 1.0f / sqrtf((float)C_EMBD * (float)T_SEQ);

    // q = GELU(x@W1q+b1q)@W2q+b2q  (same for k, v), via shared hidden buffer h
    gemm_kernel<false, 2, false><<<gM, blk>>>(x, W1q, b1q, h, C_EMBD, C_EMBD, 0, 0, 0, 1.f);
    gemm_kernel<false, 1, false><<<gM, blk>>>(h, W2q, b2q, q, C_EMBD, C_EMBD, 0, 0, 0, 1.f);
    gemm_kernel<false, 2, false><<<gM, blk>>>(x, W1k, b1k, h, C_EMBD, C_EMBD, 0, 0, 0, 1.f);
    gemm_kernel<false, 1, false><<<gM, blk>>>(h, W2k, b2k, k, C_EMBD, C_EMBD, 0, 0, 0, 1.f);
    gemm_kernel<false, 2, false><<<gM, blk>>>(x, W1v, b1v, h, C_EMBD, C_EMBD, 0, 0, 0, 1.f);
    gemm_kernel<false, 1, false><<<gM, blk>>>(h, W2v, b2v, v, C_EMBD, C_EMBD, 0, 0, 0, 1.f);

    // P = tril(q @ k^T) / sqrt(C*T)   (upper tiles skipped, never read)
    gemm_kernel<true, 3, false><<<gQK, blk>>>(q, k, nullptr, p, T_SEQ, C_EMBD,
                                              sTC, sTC, sTT, inv_scale);

    // attn_out = P @ v   (K-loop truncated causally per row-tile) -> reuse h
    gemm_kernel<false, 0, true><<<gPV, blk>>>(p, v, nullptr, h, C_EMBD, T_SEQ,
                                              sTT, sTC, sTC, 1.f);

    // LayerNorm
    ln_kernel<<<BT, blk>>>(h, lnw, lnb, out);
}